// round 13
// baseline (speedup 1.0000x reference)
#include <cuda_runtime.h>
#include <math.h>

#define ENTITY 50000
#define EMBD   256
#define HID    256
#define BATCH  64
#define LSEQ   256
#define NEDGE  800000
#define BL     (BATCH * LSEQ)   // 16384

// ---------------- scratch (device globals: no allocations allowed) ----------
__device__ float g_t0[BL * HID];
__device__ float g_t1[BL * HID];
__device__ float g_t2[BL * HID];
__device__ float g_t3[BL * HID];
__device__ float g_xi[BL * 3 * HID];
__device__ float g_support[ENTITY * HID];
__device__ float g_gnn[ENTITY * HID];
__device__ float g_h[2][BATCH * HID];   // double-buffered GRU hidden state
__device__ unsigned g_bar;              // grid-barrier counter

// ---------------- f32x2 packed-FMA helpers (sm_100+) ------------------------
__device__ __forceinline__ void fma2(unsigned long long& d,
                                     unsigned long long a,
                                     unsigned long long b) {
    asm("fma.rn.f32x2 %0, %1, %2, %0;" : "+l"(d) : "l"(a), "l"(b));
}
__device__ __forceinline__ unsigned long long dup2(float x) {
    unsigned long long r;
    asm("mov.b64 %0, {%1, %1};" : "=l"(r) : "f"(x));
    return r;
}
__device__ __forceinline__ float2 unpk(unsigned long long v) {
    float2 f;
    asm("mov.b64 {%0, %1}, %2;" : "=f"(f.x), "=f"(f.y) : "l"(v));
    return f;
}

// ---------------- generic 64x64x16 fp32 GEMM (f32x2 micro-kernel) -----------
// C[M,N] = A' @ B' (+ bias), with variants:
//   GATHER:   A'[r][k] = A[idx[r]*K + k]
//   MIX:      A'[r][k] = (1-eps)*A[r*K+k] + eps*gnn[idx[r]*HID + k]
//   TRANSB:   B'[k][n] = B[n*K + k]
//   EPSGUARD: no-op when eps[0]==0
//   RELU:     max(0, .) epilogue
// Global loads are register-double-buffered: tile k+1's LDGs issue right
// after tile k's smem stores commit, overlapping DRAM/L2 latency with the
// f32x2 compute of tile k.
// blockIdx.z batches via element strides sA/sB/sC. Requires K%16==0, N%64==0.
template <bool GATHER, bool MIX, bool TRANSB, bool EPSGUARD, bool RELU>
__global__ __launch_bounds__(256)
void gemm64k(const float* __restrict__ A, const float* __restrict__ Bm,
             float* __restrict__ C, const float* __restrict__ bias,
             const int* __restrict__ idx, const float* __restrict__ gnn,
             const float* __restrict__ epsp,
             int M, int N, int K, long sA, long sB, long sC)
{
    if constexpr (EPSGUARD) {
        if (epsp[0] == 0.0f) return;
    }
    __shared__ __align__(16) float As[16][68];
    __shared__ __align__(16) float Bs[16][68];
    __shared__ int sidx[64];

    const int tid = threadIdx.x;
    const int m0 = blockIdx.y * 64;
    const int n0 = blockIdx.x * 64;
    const long z = blockIdx.z;
    const float* Ab = A + z * sA;
    const float* Bb = Bm + z * sB;
    float* Cb = C + z * sC;

    float epsv = 0.0f, om = 1.0f;
    if constexpr (MIX) { epsv = epsp[0]; om = 1.0f - epsv; }

    if constexpr (GATHER || MIX) {
        if (tid < 64) sidx[tid] = idx[m0 + tid];
        __syncthreads();
    }

    const int ar = tid >> 2;           // A tile row 0..63
    const int ac = (tid & 3) << 2;     // A tile k-col {0,4,8,12}
    const int tx = tid & 15, ty = tid >> 4;
    const int tx4 = tx << 2, ty4 = ty << 2;

    // B-tile thread mapping (k0-independent)
    int br, bc;
    if constexpr (TRANSB) {
        br = tid >> 2;              // n-row 0..63
        bc = (tid & 3) << 2;        // k-col {0,4,8,12}
    } else {
        br = tid >> 4;              // k-row 0..15
        bc = (tid & 15) << 2;       // n-col
    }

    // ---- tile loaders ----
    auto loadA = [&](int k0) -> float4 {
        float4 av = make_float4(0.f, 0.f, 0.f, 0.f);
        if constexpr (GATHER) {
            av = *(const float4*)(Ab + (long)sidx[ar] * K + k0 + ac);
        } else if constexpr (MIX) {
            av = *(const float4*)(Ab + (long)(m0 + ar) * K + k0 + ac);
            if (epsv != 0.0f) {
                const float4 gv = *(const float4*)(gnn + (long)sidx[ar] * HID + k0 + ac);
                av.x = om * av.x + epsv * gv.x;
                av.y = om * av.y + epsv * gv.y;
                av.z = om * av.z + epsv * gv.z;
                av.w = om * av.w + epsv * gv.w;
            }
        } else {
            const int row = m0 + ar;
            if (row < M) av = *(const float4*)(Ab + (long)row * K + k0 + ac);
        }
        return av;
    };
    auto loadB = [&](int k0) -> float4 {
        if constexpr (TRANSB) {
            return *(const float4*)(Bb + (long)(n0 + br) * K + k0 + bc);
        } else {
            return *(const float4*)(Bb + (long)(k0 + br) * N + n0 + bc);
        }
    };

    unsigned long long acc[4][2];
#pragma unroll
    for (int i = 0; i < 4; ++i) { acc[i][0] = 0ull; acc[i][1] = 0ull; }

    // ---- prologue: first tile's global loads ----
    float4 av = loadA(0);
    float4 bv = loadB(0);

    for (int k0 = 0; k0 < K; k0 += 16) {
        __syncthreads();   // previous tile's compute done reading smem
        // ---- commit current tile to smem ----
        As[ac + 0][ar] = av.x;
        As[ac + 1][ar] = av.y;
        As[ac + 2][ar] = av.z;
        As[ac + 3][ar] = av.w;
        if constexpr (TRANSB) {
            Bs[bc + 0][br] = bv.x;
            Bs[bc + 1][br] = bv.y;
            Bs[bc + 2][br] = bv.z;
            Bs[bc + 3][br] = bv.w;
        } else {
            *(float4*)&Bs[br][bc] = bv;
        }
        __syncthreads();

        // ---- prefetch next tile (overlaps with compute below) ----
        if (k0 + 16 < K) {
            av = loadA(k0 + 16);
            bv = loadB(k0 + 16);
        }

        // ---- f32x2 micro-kernel: 4x4 per thread ----
#pragma unroll
        for (int kk = 0; kk < 16; ++kk) {
            const float4 a = *(const float4*)&As[kk][ty4];
            const ulonglong2 b2 = *(const ulonglong2*)&Bs[kk][tx4];
            unsigned long long d;
            d = dup2(a.x); fma2(acc[0][0], d, b2.x); fma2(acc[0][1], d, b2.y);
            d = dup2(a.y); fma2(acc[1][0], d, b2.x); fma2(acc[1][1], d, b2.y);
            d = dup2(a.z); fma2(acc[2][0], d, b2.x); fma2(acc[2][1], d, b2.y);
            d = dup2(a.w); fma2(acc[3][0], d, b2.x); fma2(acc[3][1], d, b2.y);
        }
    }

    // ---- epilogue ----
    float4 bb = make_float4(0.f, 0.f, 0.f, 0.f);
    if (bias) bb = *(const float4*)&bias[n0 + tx4];
#pragma unroll
    for (int i = 0; i < 4; ++i) {
        const int row = m0 + ty4 + i;
        if (row < M) {
            const float2 c0 = unpk(acc[i][0]);
            const float2 c1 = unpk(acc[i][1]);
            float4 v = make_float4(c0.x + bb.x, c0.y + bb.y, c1.x + bb.z, c1.y + bb.w);
            if constexpr (RELU) {
                v.x = fmaxf(v.x, 0.f); v.y = fmaxf(v.y, 0.f);
                v.z = fmaxf(v.z, 0.f); v.w = fmaxf(v.w, 0.f);
            }
            *(float4*)&Cb[(long)row * N + n0 + tx4] = v;
        }
    }
}

// ---------------- GNN helper kernels (all no-ops when eps==0) ---------------
__global__ void k_gnn_init(const float* __restrict__ bg,
                           const float* __restrict__ epsp) {
    if (epsp[0] == 0.0f) return;
    const long total = (long)ENTITY * HID;
    for (long i = (long)blockIdx.x * blockDim.x + threadIdx.x;
         i < total; i += (long)gridDim.x * blockDim.x)
        g_gnn[i] = bg[i & (HID - 1)];
}

__global__ void k_scatter(const int* __restrict__ src, const int* __restrict__ dst,
                          const float* __restrict__ w, const float* __restrict__ epsp) {
    if (epsp[0] == 0.0f) return;
    const int lane = threadIdx.x & 31;
    long wid = ((long)blockIdx.x * blockDim.x + threadIdx.x) >> 5;
    const long nw = ((long)gridDim.x * blockDim.x) >> 5;
    for (long e = wid; e < NEDGE; e += nw) {
        const int s = src[e], d = dst[e];
        const float ww = w[e];
        const float* sp = g_support + (long)s * HID;
        float* dp = g_gnn + (long)d * HID;
        for (int h = lane; h < HID; h += 32) atomicAdd(dp + h, sp[h] * ww);
    }
}

__global__ void k_leaky(const float* __restrict__ epsp) {
    if (epsp[0] == 0.0f) return;
    const long total = (long)ENTITY * HID;
    for (long i = (long)blockIdx.x * blockDim.x + threadIdx.x;
         i < total; i += (long)gridDim.x * blockDim.x) {
        const float x = g_gnn[i];
        g_gnn[i] = (x > 0.f) ? x : 0.2f * x;
    }
}

// ---------------- per-launch state init -------------------------------------
__global__ void k_init() {
    const int i = blockIdx.x * blockDim.x + threadIdx.x;
    if (i == 0) g_bar = 0u;
    if (i < BATCH * HID) g_h[0][i] = 0.f;
}

// ---------------- persistent GRU --------------------------------------------
// 128 blocks = 16 hid-groups (16 outputs each) x 8 batch-groups (8 samples).
// Whh slice (48 rows x 256) stationary in dynamic smem; h double-buffered in
// global (L2-coherent .cg accesses); grid barrier per step.
// Smem strides: 260 floats = 1040B rows -> 16B aligned AND 4-bank row stride:
//   sW rows (4 distinct per warp)  -> banks {4r..4r+3}, conflict-free LDS.128
//   sh rows (8 distinct per warp)  -> banks {4b..4b+3}, conflict-free LDS.128
#define GRU_GRID   128
#define GRU_THR    384
#define WSTRIDE    260
#define HSTRIDE    260
#define OFF_W      0
#define OFF_H      (48 * WSTRIDE)                 // 12480
#define OFF_G      (OFF_H + 8 * HSTRIDE)          // 14560  (sG[8][48])
#define OFF_B      (OFF_G + 8 * 48)               // 14944  (sbh[48])
#define GRU_SMEM   ((OFF_B + 48) * 4)             // 59968 bytes

__device__ __forceinline__ void grid_bar(unsigned target) {
    __syncthreads();
    if (threadIdx.x == 0) {
        __threadfence();                     // release: h' stores visible
        atomicAdd(&g_bar, 1u);
        while (*((volatile unsigned*)&g_bar) < target) __nanosleep(128);
        __threadfence();                     // acquire: order next-step loads
    }
    __syncthreads();
}

__global__ __launch_bounds__(GRU_THR, 1)
void k_gru(const float* __restrict__ Whh, const float* __restrict__ bhh)
{
    extern __shared__ __align__(16) float smem[];
    float* sW  = smem + OFF_W;   // [48][WSTRIDE]
    float* sh  = smem + OFF_H;   // [8][HSTRIDE]
    float* sG  = smem + OFF_G;   // [8][48]  gh (+bhh) per (batch,gate-row)
    float* sbh = smem + OFF_B;   // [48]

    const int tid = threadIdx.x;
    const int HG  = blockIdx.x & 15;  // hidden group: outputs HG*16 .. +15
    const int BG  = blockIdx.x >> 4;  // batch group:  samples BG*8 .. +7

    // ---- load Whh slice + bhh slice into smem ----
    for (int i = tid; i < 48 * 64; i += GRU_THR) {           // float4 granules
        const int r  = i >> 6;            // 0..47
        const int c4 = (i & 63) << 2;     // 0..252 step 4
        const int grow = (r >> 4) * HID + HG * 16 + (r & 15);
        *(float4*)&sW[r * WSTRIDE + c4] = *(const float4*)&Whh[(long)grow * HID + c4];
    }
    if (tid < 48) {
        const int grow = (tid >> 4) * HID + HG * 16 + (tid & 15);
        sbh[tid] = bhh[grow];
    }

    // dot-thread mapping: warp = 4 rows x 8 batches
    const int w = tid >> 5, l = tid & 31;
    const int row = w * 4 + (l >> 3);     // 0..47  (gate = row/16, j = row%16)
    const int b   = l & 7;                // 0..7
    const float* wr = &sW[row * WSTRIDE];
    const float* hb = &sh[b * HSTRIDE];

    // combiner mapping (first 128 threads): one per (b, j)
    const int cb = tid & 7, cj = tid >> 3;
    const long xbase0 = ((long)(BG * 8 + cb) * LSEQ) * (3 * HID) + HG * 16 + cj;

    for (int s = 0; s < LSEQ; ++s) {
        const int cur = s & 1, nxt = cur ^ 1;

        // ---- load h (L2-coherent) into smem ----
        for (int i = tid; i < 8 * 64; i += GRU_THR) {
            const int bb = i >> 6, c4 = (i & 63) << 2;
            const float4 v = __ldcg((const float4*)&g_h[cur][(BG * 8 + bb) * HID + c4]);
            *(float4*)&sh[bb * HSTRIDE + c4] = v;
        }

        // ---- prefetch xi for this step (DRAM latency hidden under the dot) --
        float xir = 0.f, xiz = 0.f, xin = 0.f;
        if (tid < 128) {
            const long base = xbase0 + (long)s * (3 * HID);
            xir = g_xi[base];
            xiz = g_xi[base + HID];
            xin = g_xi[base + 2 * HID];
        }
        __syncthreads();

        // ---- gh = h . Whh_row + bhh_row (LDS.128 + f32x2) ----
        unsigned long long a0 = 0ull, a1 = 0ull;
#pragma unroll
        for (int k = 0; k < HID; k += 4) {
            const ulonglong2 w2 = *(const ulonglong2*)(wr + k);
            const ulonglong2 h2 = *(const ulonglong2*)(hb + k);
            fma2(a0, w2.x, h2.x);
            fma2(a1, w2.y, h2.y);
        }
        const float2 f0 = unpk(a0), f1 = unpk(a1);
        sG[b * 48 + row] = f0.x + f0.y + f1.x + f1.y + sbh[row];
        __syncthreads();

        // ---- combine gates, write h' ----
        if (tid < 128) {
            const int gb = BG * 8 + cb;
            const float ghr = sG[cb * 48 + cj];
            const float ghz = sG[cb * 48 + 16 + cj];
            const float ghn = sG[cb * 48 + 32 + cj];
            const float r = 1.f / (1.f + __expf(-(xir + ghr)));
            const float z = 1.f / (1.f + __expf(-(xiz + ghz)));
            const float n = tanhf(xin + r * ghn);
            const float hp = sh[cb * HSTRIDE + HG * 16 + cj];
            __stcg(&g_h[nxt][gb * HID + HG * 16 + cj], (1.f - z) * n + z * hp);
        }
        grid_bar((unsigned)(s + 1) * GRU_GRID);
    }
    // final hidden state lives in g_h[0] (step 255 wrote buffer 0)
}

// ---------------- launch -----------------------------------------------------
extern "C" void kernel_launch(void* const* d_in, const int* in_sizes, int n_in,
                              void* d_out, int out_size)
{
    const int*   neighbors = (const int*)  d_in[0];
    const float* adj       = (const float*)d_in[1];
    const int*   cur_node  = (const int*)  d_in[2];
    const int*   edge_src  = (const int*)  d_in[3];
    const int*   edge_dst  = (const int*)  d_in[4];
    const float* edge_w    = (const float*)d_in[5];
    const float* emb       = (const float*)d_in[6];
    const float* Wg        = (const float*)d_in[7];
    const float* bg        = (const float*)d_in[8];
    const float* W1        = (const float*)d_in[9];
    const float* b1        = (const float*)d_in[10];
    const float* W2        = (const float*)d_in[11];
    const float* b2        = (const float*)d_in[12];
    const float* eps       = (const float*)d_in[13];
    const float* Wih       = (const float*)d_in[14];
    const float* Whh       = (const float*)d_in[15];
    const float* bih       = (const float*)d_in[16];
    const float* bhh       = (const float*)d_in[17];
    const float* fc1W      = (const float*)d_in[18];
    const float* fc1b      = (const float*)d_in[19];
    float* out = (float*)d_out;

    float *t0, *t1, *t2, *t3, *xi, *support, *gnn, *h0;
    cudaGetSymbolAddress((void**)&t0, g_t0);
    cudaGetSymbolAddress((void**)&t1, g_t1);
    cudaGetSymbolAddress((void**)&t2, g_t2);
    cudaGetSymbolAddress((void**)&t3, g_t3);
    cudaGetSymbolAddress((void**)&xi, g_xi);
    cudaGetSymbolAddress((void**)&support, g_support);
    cudaGetSymbolAddress((void**)&gnn, g_gnn);
    cudaGetSymbolAddress((void**)&h0, g_h);

    cudaFuncSetAttribute(k_gru, cudaFuncAttributeMaxDynamicSharedMemorySize, GRU_SMEM);

    // 0) per-launch state
    k_init<<<64, 256>>>();

    // 1) GNN branch (device-side no-op when eps==0)
    {
        dim3 g(HID / 64, (ENTITY + 63) / 64, 1);
        gemm64k<false, false, false, true, false><<<g, 256>>>(
            emb, Wg, support, nullptr, nullptr, nullptr, eps,
            ENTITY, HID, EMBD, 0, 0, 0);
    }
    k_gnn_init<<<1024, 256>>>(bg, eps);
    k_scatter<<<2048, 256>>>(edge_src, edge_dst, edge_w, eps);
    k_leaky<<<1024, 256>>>(eps);

    // 2) t0 = emb[neighbors] @ W1
    {
        dim3 g(HID / 64, BL / 64, 1);
        gemm64k<true, false, false, false, false><<<g, 256>>>(
            emb, W1, t0, nullptr, neighbors, nullptr, nullptr,
            BL, HID, EMBD, 0, 0, 0);
    }
    // 3) t1 = adj @ t0 + b1   (batched over B)
    {
        dim3 g(HID / 64, LSEQ / 64, BATCH);
        gemm64k<false, false, false, false, false><<<g, 256>>>(
            adj, t0, t1, b1, nullptr, nullptr, nullptr,
            LSEQ, HID, LSEQ, (long)LSEQ * LSEQ, (long)LSEQ * HID, (long)LSEQ * HID);
    }
    // 4) t2 = t1 @ W2
    {
        dim3 g(HID / 64, BL / 64, 1);
        gemm64k<false, false, false, false, false><<<g, 256>>>(
            t1, W2, t2, nullptr, nullptr, nullptr, nullptr,
            BL, HID, HID, 0, 0, 0);
    }
    // 5) t3 = adj @ t2 + b2   (batched over B)
    {
        dim3 g(HID / 64, LSEQ / 64, BATCH);
        gemm64k<false, false, false, false, false><<<g, 256>>>(
            adj, t2, t3, b2, nullptr, nullptr, nullptr,
            LSEQ, HID, LSEQ, (long)LSEQ * LSEQ, (long)LSEQ * HID, (long)LSEQ * HID);
    }
    // 6) xi = ((1-eps)*t3 + eps*gnn[cur_node]) @ Wih^T + bih
    {
        dim3 g(3 * HID / 64, BL / 64, 1);
        gemm64k<false, true, true, false, false><<<g, 256>>>(
            t3, Wih, xi, bih, cur_node, gnn, eps,
            BL, 3 * HID, HID, 0, 0, 0);
    }
    // 7) GRU over 256 steps (persistent, grid-barriered)
    k_gru<<<GRU_GRID, GRU_THR, GRU_SMEM>>>(Whh, bhh);

    // 8) out = relu(hT @ fc1W^T + fc1b)   (hT in g_h[0])
    {
        dim3 g(HID / 64, 1, 1);
        gemm64k<false, false, true, false, true><<<g, 256>>>(
            h0, fc1W, out, fc1b, nullptr, nullptr, nullptr,
            BATCH, HID, HID, 0, 0, 0);
    }
}